// round 13
// baseline (speedup 1.0000x reference)
#include <cuda_runtime.h>
#include <cuda_bf16.h>
#include <cstdint>

#define N_NODES 100000
#define E_MAX   1600000
#define FDIM 512
#define HDIM 64

// ---------------- scratch ----------------
__device__ __align__(128) float g_x1g[(size_t)N_NODES * HDIM];   // X@W1 (UNscaled)
__device__ __align__(128) float g_hs[(size_t)N_NODES * HDIM];    // relu(agg1*nd)*ns
__device__ __align__(128) float g_norm_src[N_NODES];
__device__ __align__(128) float g_norm_dst[N_NODES];
__device__ __align__(128) unsigned short g_w1ht[HDIM * FDIM];
__device__ __align__(128) unsigned short g_w1lt[HDIM * FDIM];
__device__ __align__(128) unsigned short g_w2ht[FDIM * HDIM];
__device__ __align__(128) unsigned short g_w2lt[FDIM * HDIM];
__device__ int g_cnt_in[N_NODES];
__device__ int g_cnt_out[N_NODES];
__device__ int g_row_start[N_NODES + 1];
__device__ int g_cursor[N_NODES];
__device__ int g_esrc[E_MAX];
__device__ int g_bsum[256];
__device__ int g_is64;

// ---------------- helpers ----------------
__device__ __forceinline__ uint32_t smem_to_u32(const void* p) {
    uint32_t a;
    asm("{ .reg .u64 t; cvta.to.shared.u64 t, %1; cvt.u32.u64 %0, t; }" : "=r"(a) : "l"(p));
    return a;
}
__device__ __forceinline__ void ldsm4(uint32_t* r, uint32_t addr) {
    asm volatile("ldmatrix.sync.aligned.m8n8.x4.shared.b16 {%0,%1,%2,%3}, [%4];"
                 : "=r"(r[0]), "=r"(r[1]), "=r"(r[2]), "=r"(r[3]) : "r"(addr));
}
__device__ __forceinline__ void mma_bf16(float* c, const uint32_t* a, const uint32_t* b) {
    asm volatile(
        "mma.sync.aligned.m16n8k16.row.col.f32.bf16.bf16.f32 "
        "{%0,%1,%2,%3}, {%4,%5,%6,%7}, {%8,%9}, {%0,%1,%2,%3};"
        : "+f"(c[0]), "+f"(c[1]), "+f"(c[2]), "+f"(c[3])
        : "r"(a[0]), "r"(a[1]), "r"(a[2]), "r"(a[3]), "r"(b[0]), "r"(b[1]));
}
__device__ __forceinline__ void split2(float x, float y, uint32_t& h2, uint32_t& l2) {
    __nv_bfloat162 bh = __floats2bfloat162_rn(x, y);
    float2 f = __bfloat1622float2(bh);
    __nv_bfloat162 bl = __floats2bfloat162_rn(x - f.x, y - f.y);
    h2 = reinterpret_cast<uint32_t&>(bh);
    l2 = reinterpret_cast<uint32_t&>(bl);
}
__device__ __forceinline__ void bf16split(float x, unsigned short& h, unsigned short& l) {
    __nv_bfloat16 bh = __float2bfloat16(x);
    float fh = __bfloat162float(bh);
    __nv_bfloat16 bl = __float2bfloat16(x - fh);
    h = __bfloat16_as_ushort(bh);
    l = __bfloat16_as_ushort(bl);
}
__device__ __forceinline__ int load_idx(const void* p, int e, int is64) {
    if (is64) return (int)__ldg(reinterpret_cast<const long long*>(p) + e);
    return __ldg(reinterpret_cast<const int*>(p) + e);
}

// ---------------- zero counters + index width probe (fused) ----------------
__global__ __launch_bounds__(256) void zero_counts_kernel(const int* __restrict__ src32,
                                                          const int* __restrict__ dst32,
                                                          int n, int E) {
    int i = blockIdx.x * blockDim.x + threadIdx.x;
    if (i < n) { g_cnt_in[i] = 0; g_cnt_out[i] = 0; }
    if (i == 0) {
        int m = E < 256 ? E : 256;
        int is64 = 1;
        for (int k = 0; k < m; k++) {
            if (src32[2 * k + 1] != 0 || dst32[2 * k + 1] != 0) { is64 = 0; break; }
        }
        g_is64 = is64;
    }
}

// ---------------- weight pre-conversion ----------------
__global__ __launch_bounds__(256) void wconv_kernel(const float* __restrict__ W1,
                                                    const float* __restrict__ W2) {
    int i = blockIdx.x * blockDim.x + threadIdx.x;
    if (i < FDIM * HDIM) {
        unsigned short h, l;
        {
            int k = i >> 6, n = i & 63;
            bf16split(__ldg(&W1[i]), h, l);
            g_w1ht[n * FDIM + k] = h;
            g_w1lt[n * FDIM + k] = l;
        }
        {
            int k = i >> 9, n = i & 511;
            bf16split(__ldg(&W2[i]), h, l);
            g_w2ht[n * HDIM + k] = h;
            g_w2lt[n * HDIM + k] = l;
        }
    }
}

// ---------------- graph build ----------------
__global__ __launch_bounds__(256) void hist_kernel(const void* __restrict__ src,
                                                   const void* __restrict__ dst, int E) {
    int e = blockIdx.x * blockDim.x + threadIdx.x;
    if (e < E) {
        int is64 = g_is64;
        atomicAdd(&g_cnt_out[load_idx(src, e, is64)], 1);
        atomicAdd(&g_cnt_in[load_idx(dst, e, is64)], 1);
    }
}
__global__ __launch_bounds__(256) void scan1_kernel(int n) {
    __shared__ int sh[256];
    int tid = threadIdx.x;
    int base = blockIdx.x * 1024 + tid * 4;
    int v[4];
#pragma unroll
    for (int k = 0; k < 4; k++) v[k] = (base + k < n) ? g_cnt_in[base + k] : 0;
    int t = v[0] + v[1] + v[2] + v[3];
    sh[tid] = t;
    __syncthreads();
    for (int off = 1; off < 256; off <<= 1) {
        int x = (tid >= off) ? sh[tid - off] : 0;
        __syncthreads();
        sh[tid] += x;
        __syncthreads();
    }
    int run = sh[tid] - t;
#pragma unroll
    for (int k = 0; k < 4; k++) {
        if (base + k < n) g_row_start[base + k] = run;
        run += v[k];
    }
    if (tid == 255) g_bsum[blockIdx.x] = sh[255];
}
__global__ void scan2_kernel(int nb) {
    __shared__ int sh[256];
    int t = threadIdx.x;
    int v = (t < nb) ? g_bsum[t] : 0;
    sh[t] = v;
    __syncthreads();
    for (int off = 1; off < 256; off <<= 1) {
        int x = (t >= off) ? sh[t - off] : 0;
        __syncthreads();
        sh[t] += x;
        __syncthreads();
    }
    if (t < nb) g_bsum[t] = sh[t] - v;
}
__global__ __launch_bounds__(256) void scan3_kernel(int n, int E) {
    int i = blockIdx.x * blockDim.x + threadIdx.x;
    if (i < n) {
        int v = g_row_start[i] + g_bsum[i >> 10];
        g_row_start[i] = v;
        g_cursor[i] = v;
        g_norm_src[i] = rsqrtf(fmaxf((float)g_cnt_out[i], 1.0f));
        g_norm_dst[i] = rsqrtf(fmaxf((float)g_cnt_in[i], 1.0f));
    }
    if (i == 0) g_row_start[n] = E;
}
__global__ __launch_bounds__(256) void fill_kernel(const void* __restrict__ src,
                                                   const void* __restrict__ dst, int E) {
    int e = blockIdx.x * blockDim.x + threadIdx.x;
    if (e < E) {
        int is64 = g_is64;
        int s = load_idx(src, e, is64);
        int d = load_idx(dst, e, is64);
        int pos = atomicAdd(&g_cursor[d], 1);
        g_esrc[pos] = s;
    }
}

// ---------------- agg0: hs = relu((sum ns[sa]*x1g[sa]) * nd) * ns ----------------
__global__ __launch_bounds__(256) void agg0_kernel(const float* __restrict__ msg,
                                                   float* __restrict__ outf, int n) {
    int node = blockIdx.x * 16 + (threadIdx.x >> 4);
    int c = threadIdx.x & 15;
    if (node >= n) return;
    int j = g_row_start[node];
    int s1 = g_row_start[node + 1];
    float4 acc = make_float4(0.f, 0.f, 0.f, 0.f);
    for (; j + 1 < s1; j += 2) {
        int sa = __ldg(&g_esrc[j]);
        int sb = __ldg(&g_esrc[j + 1]);
        float4 va = __ldg(reinterpret_cast<const float4*>(msg + (size_t)sa * HDIM + c * 4));
        float4 vb = __ldg(reinterpret_cast<const float4*>(msg + (size_t)sb * HDIM + c * 4));
        float na = __ldg(&g_norm_src[sa]);
        float nb = __ldg(&g_norm_src[sb]);
        acc.x = fmaf(va.x, na, acc.x); acc.y = fmaf(va.y, na, acc.y);
        acc.z = fmaf(va.z, na, acc.z); acc.w = fmaf(va.w, na, acc.w);
        acc.x = fmaf(vb.x, nb, acc.x); acc.y = fmaf(vb.y, nb, acc.y);
        acc.z = fmaf(vb.z, nb, acc.z); acc.w = fmaf(vb.w, nb, acc.w);
    }
    if (j < s1) {
        int sa = __ldg(&g_esrc[j]);
        float4 va = __ldg(reinterpret_cast<const float4*>(msg + (size_t)sa * HDIM + c * 4));
        float na = __ldg(&g_norm_src[sa]);
        acc.x = fmaf(va.x, na, acc.x); acc.y = fmaf(va.y, na, acc.y);
        acc.z = fmaf(va.z, na, acc.z); acc.w = fmaf(va.w, na, acc.w);
    }
    float nd = g_norm_dst[node];
    float ns = g_norm_src[node];
    float4 o;
    o.x = fmaxf(acc.x * nd, 0.f) * ns;
    o.y = fmaxf(acc.y * nd, 0.f) * ns;
    o.z = fmaxf(acc.z * nd, 0.f) * ns;
    o.w = fmaxf(acc.w * nd, 0.f) * ns;
    reinterpret_cast<float4*>(outf)[(size_t)node * 16 + c] = o;
}

// ---------------- GEMM1: C[M,64] = A(fp32)[M,512] @ W1 (UNscaled output) ----------------
#define AST 40
__global__ __launch_bounds__(256) void gemm1_kernel(const float* __restrict__ A,
                                                    const unsigned short* __restrict__ Bth,
                                                    const unsigned short* __restrict__ Btl,
                                                    float* __restrict__ C, int M) {
    __shared__ __align__(16) unsigned short sAh[128 * AST];
    __shared__ __align__(16) unsigned short sAl[128 * AST];
    __shared__ __align__(16) unsigned short sBh[64 * AST];
    __shared__ __align__(16) unsigned short sBl[64 * AST];

    const int tid = threadIdx.x;
    const int wid = tid >> 5, lid = tid & 31;
    const int wm = wid & 3, wn = wid >> 2;
    const int block_m = blockIdx.x * 128;

    float acc[2][4][4];
#pragma unroll
    for (int i = 0; i < 2; i++)
#pragma unroll
        for (int j = 0; j < 4; j++)
#pragma unroll
            for (int q = 0; q < 4; q++) acc[i][j][q] = 0.f;

    const uint32_t aH = smem_to_u32(sAh);
    const uint32_t aL = smem_to_u32(sAl);
    const uint32_t bH = smem_to_u32(sBh);
    const uint32_t bL = smem_to_u32(sBl);

    const int b_n = tid >> 2, b_k8 = (tid & 3) * 8;
    for (int k0 = 0; k0 < FDIM; k0 += 32) {
#pragma unroll
        for (int it = 0; it < 4; it++) {
            int f = it * 256 + tid;
            int r = f >> 3, c4 = f & 7;
            int gr = block_m + r;
            float4 v = make_float4(0.f, 0.f, 0.f, 0.f);
            if (gr < M)
                v = __ldg(reinterpret_cast<const float4*>(A + (size_t)gr * FDIM + k0 + c4 * 4));
            uint32_t h01, l01, h23, l23;
            split2(v.x, v.y, h01, l01);
            split2(v.z, v.w, h23, l23);
            *reinterpret_cast<uint2*>(&sAh[r * AST + c4 * 4]) = make_uint2(h01, h23);
            *reinterpret_cast<uint2*>(&sAl[r * AST + c4 * 4]) = make_uint2(l01, l23);
        }
        {
            const size_t go = (size_t)b_n * FDIM + k0 + b_k8;
            uint4 vh = __ldg(reinterpret_cast<const uint4*>(Bth + go));
            uint4 vl = __ldg(reinterpret_cast<const uint4*>(Btl + go));
            *reinterpret_cast<uint4*>(&sBh[b_n * AST + b_k8]) = vh;
            *reinterpret_cast<uint4*>(&sBl[b_n * AST + b_k8]) = vl;
        }
        __syncthreads();

#pragma unroll
        for (int ks = 0; ks < 32; ks += 16) {
            uint32_t ah[2][4], al[2][4], bh[4][2], bl[4][2];
#pragma unroll
            for (int mf = 0; mf < 2; mf++) {
                uint32_t rowA = wm * 32 + mf * 16 + (lid & 15);
                uint32_t off = (rowA * AST + ks + (lid >> 4) * 8) * 2;
                ldsm4(ah[mf], aH + off);
                ldsm4(al[mf], aL + off);
            }
#pragma unroll
            for (int p = 0; p < 2; p++) {
                uint32_t nrow = wn * 32 + p * 16 + ((lid >> 4) & 1) * 8 + (lid & 7);
                uint32_t off = (nrow * AST + ks + ((lid >> 3) & 1) * 8) * 2;
                uint32_t r[4];
                ldsm4(r, bH + off);
                bh[2 * p][0] = r[0]; bh[2 * p][1] = r[1];
                bh[2 * p + 1][0] = r[2]; bh[2 * p + 1][1] = r[3];
                ldsm4(r, bL + off);
                bl[2 * p][0] = r[0]; bl[2 * p][1] = r[1];
                bl[2 * p + 1][0] = r[2]; bl[2 * p + 1][1] = r[3];
            }
#pragma unroll
            for (int mf = 0; mf < 2; mf++)
#pragma unroll
                for (int nf = 0; nf < 4; nf++) {
                    mma_bf16(acc[mf][nf], ah[mf], bh[nf]);
                    mma_bf16(acc[mf][nf], ah[mf], bl[nf]);
                    mma_bf16(acc[mf][nf], al[mf], bh[nf]);
                }
        }
        __syncthreads();
    }

    int lrow = lid >> 2, lcol = (lid & 3) * 2;
#pragma unroll
    for (int mf = 0; mf < 2; mf++)
#pragma unroll
        for (int half = 0; half < 2; half++) {
            int row = block_m + wm * 32 + mf * 16 + lrow + half * 8;
            if (row < M) {
#pragma unroll
                for (int nf = 0; nf < 4; nf++) {
                    int col = wn * 32 + nf * 8 + lcol;
                    float2 o = make_float2(acc[mf][nf][half * 2],
                                           acc[mf][nf][half * 2 + 1]);
                    *reinterpret_cast<float2*>(C + (size_t)row * HDIM + col) = o;
                }
            }
        }
}

// ---------------- FUSED agg1 + GEMM2: out[M,512] = (S·hs · nd) @ W2 ----------------
// Phase 1: CSR-aggregate 128 rows directly into SMEM A tiles (bf16 hi/lo split).
// Phase 2: loop over 8 N-tiles of W2 with A resident.
#define AST2 72
#define G2_SMEM (2 * 128 * AST2 * 2 + 2 * 64 * AST2 * 2)
__global__ __launch_bounds__(256) void agg_gemm2_kernel(const float* __restrict__ hs,
                                                        const unsigned short* __restrict__ Bth,
                                                        const unsigned short* __restrict__ Btl,
                                                        float* __restrict__ C, int M) {
    extern __shared__ __align__(16) unsigned short dyn[];
    unsigned short* sAh = dyn;
    unsigned short* sAl = sAh + 128 * AST2;
    unsigned short* sBh = sAl + 128 * AST2;
    unsigned short* sBl = sBh + 64 * AST2;

    const int tid = threadIdx.x;
    const int wid = tid >> 5, lid = tid & 31;
    const int wm = wid & 3, wn = wid >> 2;
    const int block_m = blockIdx.x * 128;

    const uint32_t aH = smem_to_u32(sAh);
    const uint32_t aL = smem_to_u32(sAl);
    const uint32_t bH = smem_to_u32(sBh);
    const uint32_t bL = smem_to_u32(sBl);

    // ---- Phase 1: aggregate 128 rows (16 threads/node, 8 groups) ----
    {
        const int c = tid & 15;           // float4 chunk
        const int ng = tid >> 4;          // node group 0..15
#pragma unroll
        for (int it = 0; it < 8; it++) {
            int r = it * 16 + ng;
            int node = block_m + r;
            float4 acc = make_float4(0.f, 0.f, 0.f, 0.f);
            if (node < M) {
                int j = __ldg(&g_row_start[node]);
                int s1 = __ldg(&g_row_start[node + 1]);
                for (; j + 1 < s1; j += 2) {
                    int sa = __ldg(&g_esrc[j]);
                    int sb = __ldg(&g_esrc[j + 1]);
                    float4 va = __ldg(reinterpret_cast<const float4*>(hs + (size_t)sa * HDIM + c * 4));
                    float4 vb = __ldg(reinterpret_cast<const float4*>(hs + (size_t)sb * HDIM + c * 4));
                    acc.x += va.x; acc.y += va.y; acc.z += va.z; acc.w += va.w;
                    acc.x += vb.x; acc.y += vb.y; acc.z += vb.z; acc.w += vb.w;
                }
                if (j < s1) {
                    int sa = __ldg(&g_esrc[j]);
                    float4 va = __ldg(reinterpret_cast<const float4*>(hs + (size_t)sa * HDIM + c * 4));
                    acc.x += va.x; acc.y += va.y; acc.z += va.z; acc.w += va.w;
                }
                float nd = __ldg(&g_norm_dst[node]);
                acc.x *= nd; acc.y *= nd; acc.z *= nd; acc.w *= nd;
            }
            uint32_t h01, l01, h23, l23;
            split2(acc.x, acc.y, h01, l01);
            split2(acc.z, acc.w, h23, l23);
            *reinterpret_cast<uint2*>(&sAh[r * AST2 + c * 4]) = make_uint2(h01, h23);
            *reinterpret_cast<uint2*>(&sAl[r * AST2 + c * 4]) = make_uint2(l01, l23);
        }
    }

    int lrow = lid >> 2, lcol = (lid & 3) * 2;

    // ---- Phase 2: N-tile loop with A resident ----
    for (int nt = 0; nt < FDIM / 64; nt++) {
        const int n0 = nt * 64;
        __syncthreads();  // A ready (first) / previous tile's MMAs done (later)
#pragma unroll
        for (int it = 0; it < 2; it++) {
            int u = it * 256 + tid;
            int r = u >> 3, q8 = (u & 7) * 8;
            size_t go = (size_t)(n0 + r) * HDIM + q8;
            uint4 vh = __ldg(reinterpret_cast<const uint4*>(Bth + go));
            uint4 vl = __ldg(reinterpret_cast<const uint4*>(Btl + go));
            *reinterpret_cast<uint4*>(&sBh[r * AST2 + q8]) = vh;
            *reinterpret_cast<uint4*>(&sBl[r * AST2 + q8]) = vl;
        }
        __syncthreads();

        float acc[2][4][4];
#pragma unroll
        for (int i = 0; i < 2; i++)
#pragma unroll
            for (int j = 0; j < 4; j++)
#pragma unroll
                for (int q = 0; q < 4; q++) acc[i][j][q] = 0.f;

#pragma unroll
        for (int ks = 0; ks < 64; ks += 16) {
            uint32_t ah[2][4], al[2][4], bh[4][2], bl[4][2];
#pragma unroll
            for (int mf = 0; mf < 2; mf++) {
                uint32_t rowA = wm * 32 + mf * 16 + (lid & 15);
                uint32_t off = (rowA * AST2 + ks + (lid >> 4) * 8) * 2;
                ldsm4(ah[mf], aH + off);
                ldsm4(al[mf], aL + off);
            }
#pragma unroll
            for (int p = 0; p < 2; p++) {
                uint32_t nrow = wn * 32 + p * 16 + ((lid >> 4) & 1) * 8 + (lid & 7);
                uint32_t off = (nrow * AST2 + ks + ((lid >> 3) & 1) * 8) * 2;
                uint32_t r[4];
                ldsm4(r, bH + off);
                bh[2 * p][0] = r[0]; bh[2 * p][1] = r[1];
                bh[2 * p + 1][0] = r[2]; bh[2 * p + 1][1] = r[3];
                ldsm4(r, bL + off);
                bl[2 * p][0] = r[0]; bl[2 * p][1] = r[1];
                bl[2 * p + 1][0] = r[2]; bl[2 * p + 1][1] = r[3];
            }
#pragma unroll
            for (int mf = 0; mf < 2; mf++)
#pragma unroll
                for (int nf = 0; nf < 4; nf++) {
                    mma_bf16(acc[mf][nf], ah[mf], bh[nf]);
                    mma_bf16(acc[mf][nf], ah[mf], bl[nf]);
                    mma_bf16(acc[mf][nf], al[mf], bh[nf]);
                }
        }

#pragma unroll
        for (int mf = 0; mf < 2; mf++)
#pragma unroll
            for (int half = 0; half < 2; half++) {
                int row = block_m + wm * 32 + mf * 16 + lrow + half * 8;
                if (row < M) {
#pragma unroll
                    for (int nf = 0; nf < 4; nf++) {
                        int col = n0 + wn * 32 + nf * 8 + lcol;
                        float2 o = make_float2(acc[mf][nf][half * 2],
                                               acc[mf][nf][half * 2 + 1]);
                        *reinterpret_cast<float2*>(C + (size_t)row * FDIM + col) = o;
                    }
                }
            }
    }
}

// ---------------- streams/events (created once) ----------------
static cudaStream_t g_s2;
static cudaEvent_t g_evF, g_evJ;
static struct StreamInit {
    StreamInit() {
        cudaStreamCreateWithFlags(&g_s2, cudaStreamNonBlocking);
        cudaEventCreateWithFlags(&g_evF, cudaEventDisableTiming);
        cudaEventCreateWithFlags(&g_evJ, cudaEventDisableTiming);
    }
} g_stream_init;

// ---------------- launch ----------------
extern "C" void kernel_launch(void* const* d_in, const int* in_sizes, int n_in,
                              void* d_out, int out_size) {
    const float* features = (const float*)d_in[0];
    const void* src = d_in[1];
    const void* dst = d_in[2];
    const float* W1 = (const float*)d_in[3];
    const float* W2 = (const float*)d_in[4];
    float* out = (float*)d_out;

    const int N = N_NODES;
    const int E = in_sizes[1];

    float *p_x1g, *p_hs;
    unsigned short *p_w1ht, *p_w1lt, *p_w2ht, *p_w2lt;
    cudaGetSymbolAddress((void**)&p_x1g, g_x1g);
    cudaGetSymbolAddress((void**)&p_hs, g_hs);
    cudaGetSymbolAddress((void**)&p_w1ht, g_w1ht);
    cudaGetSymbolAddress((void**)&p_w1lt, g_w1lt);
    cudaGetSymbolAddress((void**)&p_w2ht, g_w2ht);
    cudaGetSymbolAddress((void**)&p_w2lt, g_w2lt);

    cudaFuncSetAttribute(agg_gemm2_kernel, cudaFuncAttributeMaxDynamicSharedMemorySize, G2_SMEM);

    const int nb_scan = (N + 1023) / 1024;
    const int mtiles = (N + 127) / 128;

    // ---- fork: wconv + GEMM1 on side stream ----
    cudaEventRecord(g_evF, 0);
    cudaStreamWaitEvent(g_s2, g_evF, 0);
    wconv_kernel<<<(FDIM * HDIM + 255) / 256, 256, 0, g_s2>>>(W1, W2);
    gemm1_kernel<<<mtiles, 256, 0, g_s2>>>(features, p_w1ht, p_w1lt, p_x1g, N);
    cudaEventRecord(g_evJ, g_s2);

    // ---- main stream: graph build ----
    zero_counts_kernel<<<(N + 255) / 256, 256>>>((const int*)src, (const int*)dst, N, E);
    hist_kernel<<<(E + 255) / 256, 256>>>(src, dst, E);
    scan1_kernel<<<nb_scan, 256>>>(N);
    scan2_kernel<<<1, 256>>>(nb_scan);
    scan3_kernel<<<(N + 255) / 256, 256>>>(N, E);
    fill_kernel<<<(E + 255) / 256, 256>>>(src, dst, E);

    // ---- join, then agg0 + fused agg1/GEMM2 ----
    cudaStreamWaitEvent(0, g_evJ, 0);
    agg0_kernel<<<(N + 15) / 16, 256>>>(p_x1g, p_hs, N);
    agg_gemm2_kernel<<<mtiles, 256, G2_SMEM>>>(p_hs, p_w2ht, p_w2lt, out, N);
}